// round 16
// baseline (speedup 1.0000x reference)
#include <cuda_runtime.h>
#include <cuda_fp16.h>
#include <cstdint>

#define N_NODES 100000
#define N_EDGES 2000000
#define DIM     64
#define F_IN    128
#define R_REL   64
#define ER_REL  2048
#define RF_REL  64
#define NCLS    16

// ---------------- scratch (static device memory; no allocations) ----------------
__device__ __align__(16) float g_agg[N_NODES * DIM];       // scatter accumulator
__device__ __align__(16) __half2 g_x0h[N_NODES * DIM / 2]; // fp16 mirror of x0 (proj out)
__device__ __align__(16) __half2 g_x1h[N_NODES * DIM / 2]; // fp16 mirror of x1 (conv1 out)
__device__ int g_deg[N_NODES];
__device__ __align__(16) float g_wrel[R_REL * DIM];        // per-relation edge weights
__device__ __align__(16) unsigned g_pk[N_EDGES];           // packed (src<<6)|etype
__device__ __align__(16) unsigned g_Bsw[64 * 64];          // fc1 as fp16x2, transposed + swizzled

// ---------------- helpers ----------------
__device__ __forceinline__ void red_add_v4(float* addr, float a, float b, float c, float d) {
    asm volatile("red.global.add.v4.f32 [%0], {%1, %2, %3, %4};"
                 :: "l"(addr), "f"(a), "f"(b), "f"(c), "f"(d)
                 : "memory");
}
__device__ __forceinline__ void red_add_s32(int* addr, int v) {
    asm volatile("red.global.add.s32 [%0], %1;" :: "l"(addr), "r"(v) : "memory");
}
__device__ __forceinline__ void mma16816(float* d, const unsigned* a, const unsigned* b) {
    asm volatile("mma.sync.aligned.m16n8k16.row.col.f32.f16.f16.f32 "
                 "{%0,%1,%2,%3}, {%4,%5,%6,%7}, {%8,%9}, {%0,%1,%2,%3};"
                 : "+f"(d[0]), "+f"(d[1]), "+f"(d[2]), "+f"(d[3])
                 : "r"(a[0]), "r"(a[1]), "r"(a[2]), "r"(a[3]),
                   "r"(b[0]), "r"(b[1]));
}

// ---------------- fused init: pack edges + deg count + zero agg/deg ------------
// NOTE: deg is zeroed by the first N_NODES threads before any red_add could
// race only within this same kernel; to stay safe, degree REDs target g_deg
// only AFTER the zeroing pass of a *previous* grid-stride? -> Instead we zero
// deg here and count in a second pass below (grid-stride, same kernel would
// race). Keep it simple: zero in this kernel is done by threads i<N_NODES
// while counting threads also run -> RACE. So: deg zero moved to its own tiny
// region: we zero deg FIRST via the same threads before a grid sync is not
// available -> use separate kernel ordering instead (deg_kernel after init).
__global__ void init_kernel(const int* __restrict__ src,
                            const int* __restrict__ et) {
    int i = blockIdx.x * blockDim.x + threadIdx.x;
    if (i < N_EDGES)
        g_pk[i] = ((unsigned)__ldg(src + i) << 6) | (unsigned)__ldg(et + i);
    if (i < N_NODES * DIM / 4)
        ((float4*)g_agg)[i] = make_float4(0.f, 0.f, 0.f, 0.f);
    if (i < N_NODES) g_deg[i] = 0;
}

// degree count (separate launch; ordered after init's zeroing)
__global__ void deg_kernel(const int* __restrict__ dst) {
    int e = blockIdx.x * blockDim.x + threadIdx.x;
    if (e < N_EDGES) red_add_s32(&g_deg[__ldg(dst + e)], 1);
}

// Merged: block 0 = relation conv + w_rel table; blocks 1-4 = prep_b.
__global__ void relprep_kernel(const float* __restrict__ rel_x,
                               const int*   __restrict__ rel_ei,
                               const float* __restrict__ rel_ea,
                               const float* __restrict__ W_nn,
                               const float* __restrict__ b_nn,
                               const float* __restrict__ fc1) {
    if (blockIdx.x > 0) {
        // prep_b: fc1 [128,64] fp32 -> fp16x2 [n][k2] transposed + swizzled
        int i = (blockIdx.x - 1) * 1024 + threadIdx.x;   // 4096 total
        int k2 = i >> 6, nn = i & 63;
        __half2 hh = __floats2half2_rn(fc1[(2 * k2) * DIM + nn],
                                       fc1[(2 * k2 + 1) * DIM + nn]);
        g_Bsw[nn * 64 + (k2 ^ ((nn & 7) << 2))] = *(unsigned*)&hh;
        return;
    }

    __shared__ __align__(16) float h[R_REL * RF_REL];
    __shared__ __align__(16) float A[R_REL * R_REL];
    __shared__ float cnt[R_REL];
    int tid = threadIdx.x;  // 1024

    for (int i = tid; i < R_REL * RF_REL; i += 1024) { h[i] = rel_x[i]; A[i] = 0.f; }
    if (tid < R_REL) cnt[tid] = 0.f;
    __syncthreads();

    for (int e = tid; e < ER_REL; e += 1024) {
        int sr = rel_ei[e];
        int dr = rel_ei[ER_REL + e];
        float a = rel_ea[e];
        atomicAdd(&A[dr * R_REL + sr], a);
        atomicAdd(&cnt[dr], 1.0f);
    }
    __syncthreads();

    int r  = tid >> 4;
    int c4 = (tid & 15) * 4;
    float inv = 1.0f / fmaxf(cnt[r], 1.0f);

    #pragma unroll
    for (int it = 0; it < 2; ++it) {
        float4 acc = make_float4(0.f, 0.f, 0.f, 0.f);
        #pragma unroll 8
        for (int k = 0; k < R_REL; ++k) {
            float a = A[r * R_REL + k];
            float4 hv = *(const float4*)&h[k * RF_REL + c4];
            acc.x += a * hv.x; acc.y += a * hv.y;
            acc.z += a * hv.z; acc.w += a * hv.w;
        }
        __syncthreads();
        float4 hv = *(const float4*)&h[r * RF_REL + c4];
        hv.x = fmaxf(hv.x + acc.x * inv, 0.f);
        hv.y = fmaxf(hv.y + acc.y * inv, 0.f);
        hv.z = fmaxf(hv.z + acc.z * inv, 0.f);
        hv.w = fmaxf(hv.w + acc.w * inv, 0.f);
        *(float4*)&h[r * RF_REL + c4] = hv;
        __syncthreads();
    }

    for (int i = tid; i < RF_REL * DIM; i += 1024) A[i] = W_nn[i];
    __syncthreads();
    float4 acc = make_float4(b_nn[c4], b_nn[c4 + 1], b_nn[c4 + 2], b_nn[c4 + 3]);
    #pragma unroll 8
    for (int k = 0; k < RF_REL; ++k) {
        float hv = h[r * RF_REL + k];
        float4 wv = *(const float4*)&A[k * DIM + c4];
        acc.x += hv * wv.x; acc.y += hv * wv.y;
        acc.z += hv * wv.z; acc.w += hv * wv.w;
    }
    *(float4*)&g_wrel[r * DIM + c4] = acc;
}

// Tensor-core proj, 64-node CTA; B tile copied pre-swizzled from g_Bsw.
__global__ void __launch_bounds__(256)
proj_kernel(const float* __restrict__ x_in) {
    __shared__ __align__(16) unsigned As[64 * 64];   // 16 KB
    __shared__ __align__(16) unsigned Bs[64 * 64];   // 16 KB
    int tid = threadIdx.x;  // 256
    int base = blockIdx.x * 64;

    #pragma unroll
    for (int it = 0; it < 8; ++it) {
        int i = tid + it * 256;
        int r = i >> 5, c4 = i & 31;
        int n = base + r;
        float4 v = (n < N_NODES) ? *(const float4*)(x_in + (size_t)n * F_IN + c4 * 4)
                                 : make_float4(0.f, 0.f, 0.f, 0.f);
        __half2 h0 = __floats2half2_rn(v.x, v.y);
        __half2 h1 = __floats2half2_rn(v.z, v.w);
        int k2  = c4 * 2;
        int k2s = k2 ^ ((r & 7) << 2);
        *(uint2*)&As[r * 64 + k2s] = make_uint2(*(unsigned*)&h0, *(unsigned*)&h1);
    }
    #pragma unroll
    for (int it = 0; it < 4; ++it) {
        int i = tid + it * 256;
        ((uint4*)Bs)[i] = __ldg((const uint4*)g_Bsw + i);
    }
    __syncthreads();

    int w    = tid >> 5;
    int lane = tid & 31;
    int g = lane >> 2, c = lane & 3;
    int wm = w & 1, wn = w >> 1;       // 2 (M) x 4 (N)
    int sw = g << 2;

    float acc[2][2][4];
    #pragma unroll
    for (int mt = 0; mt < 2; ++mt)
        #pragma unroll
        for (int nt = 0; nt < 2; ++nt)
            #pragma unroll
            for (int x = 0; x < 4; ++x) acc[mt][nt][x] = 0.f;

    #pragma unroll
    for (int ks = 0; ks < 8; ++ks) {
        int k2a = (8 * ks + c)     ^ sw;
        int k2b = (8 * ks + c + 4) ^ sw;
        unsigned a[2][4];
        #pragma unroll
        for (int mt = 0; mt < 2; ++mt) {
            int r0 = wm * 32 + mt * 16 + g;
            a[mt][0] = As[r0 * 64 + k2a];
            a[mt][1] = As[(r0 + 8) * 64 + k2a];
            a[mt][2] = As[r0 * 64 + k2b];
            a[mt][3] = As[(r0 + 8) * 64 + k2b];
        }
        unsigned b[2][2];
        #pragma unroll
        for (int nt = 0; nt < 2; ++nt) {
            int n0 = wn * 16 + nt * 8 + g;
            b[nt][0] = Bs[n0 * 64 + k2a];
            b[nt][1] = Bs[n0 * 64 + k2b];
        }
        #pragma unroll
        for (int mt = 0; mt < 2; ++mt)
            #pragma unroll
            for (int nt = 0; nt < 2; ++nt)
                mma16816(acc[mt][nt], a[mt], b[nt]);
    }

    #pragma unroll
    for (int mt = 0; mt < 2; ++mt) {
        int r0 = base + wm * 32 + mt * 16 + g;
        #pragma unroll
        for (int nt = 0; nt < 2; ++nt) {
            int col2 = wn * 8 + nt * 4 + c;
            if (r0 < N_NODES)
                g_x0h[(size_t)r0 * 32 + col2] =
                    __floats2half2_rn(acc[mt][nt][0], acc[mt][nt][1]);
            if (r0 + 8 < N_NODES)
                g_x0h[(size_t)(r0 + 8) * 32 + col2] =
                    __floats2half2_rn(acc[mt][nt][2], acc[mt][nt][3]);
        }
    }
}

// Push edge sweep, 4-edge pipelined (R8-proven), now branch-free (no deg).
__global__ void edge_kernel(const int* __restrict__ dst, int which_x) {
    __shared__ __align__(16) float ws[R_REL * DIM];  // 16 KB
    for (int i = threadIdx.x; i < R_REL * DIM; i += blockDim.x) ws[i] = g_wrel[i];
    __syncthreads();

    const __half2* __restrict__ xh = which_x ? g_x1h : g_x0h;

    int G    = (gridDim.x * blockDim.x) >> 4;
    int g    = (blockIdx.x * blockDim.x + threadIdx.x) >> 4;
    int lane = threadIdx.x & 15;
    const int NQUADS = N_EDGES / 4;

    for (int q = g; q < NQUADS; q += G) {
        int e = q * 4;
        uint4 pk = __ldg((const uint4*)(g_pk + e));   // broadcast within group
        uint4 dd = *(const uint4*)(dst + e);          // broadcast within group

        uint2 p0 = __ldg((const uint2*)(xh + (size_t)(pk.x >> 6) * 32 + lane * 2));
        uint2 p1 = __ldg((const uint2*)(xh + (size_t)(pk.y >> 6) * 32 + lane * 2));
        uint2 p2 = __ldg((const uint2*)(xh + (size_t)(pk.z >> 6) * 32 + lane * 2));
        uint2 p3 = __ldg((const uint2*)(xh + (size_t)(pk.w >> 6) * 32 + lane * 2));

        unsigned pks[4] = {pk.x, pk.y, pk.z, pk.w};
        unsigned dds[4] = {dd.x, dd.y, dd.z, dd.w};
        uint2    pps[4] = {p0, p1, p2, p3};
        #pragma unroll
        for (int j = 0; j < 4; ++j) {
            float2 f0 = __half22float2(*(__half2*)&pps[j].x);
            float2 f1 = __half22float2(*(__half2*)&pps[j].y);
            float4 wv = *(const float4*)&ws[(pks[j] & 63u) * DIM + lane * 4];
            red_add_v4(g_agg + (size_t)dds[j] * DIM + lane * 4,
                       f0.x * wv.x, f0.y * wv.y, f1.x * wv.z, f1.y * wv.w);
        }
    }
}

// finish (layer 1 only): x1 = tanh(agg/deg + b1) -> fp16 mirror; re-zero agg.
__global__ void finish_kernel(const float* __restrict__ b) {
    int i = blockIdx.x * blockDim.x + threadIdx.x;
    if (i >= N_NODES * (DIM / 4)) return;
    int n = i >> 4, c4 = (i & 15) * 4;
    float4 v = ((const float4*)g_agg)[i];
    int d = g_deg[n];
    float inv = 1.0f / (float)(d > 0 ? d : 1);
    float4 bb = *(const float4*)(b + c4);
    v.x = tanhf(v.x * inv + bb.x);
    v.y = tanhf(v.y * inv + bb.y);
    v.z = tanhf(v.z * inv + bb.z);
    v.w = tanhf(v.w * inv + bb.w);
    __half2 h0 = __floats2half2_rn(v.x, v.y);
    __half2 h1 = __floats2half2_rn(v.z, v.w);
    uint2 p = make_uint2(*(uint32_t*)&h0, *(uint32_t*)&h1);
    *(uint2*)(g_x1h + (size_t)n * 32 + (c4 >> 1)) = p;
    ((float4*)g_agg)[i] = make_float4(0.f, 0.f, 0.f, 0.f);
}

// Fused finish2 + out:  out = tanh(agg/deg + b2) @ fc2_w + fc2_b.
__global__ void out_kernel(const float* __restrict__ b2,
                           const float* __restrict__ fc2w,
                           const float* __restrict__ fc2b,
                           float* __restrict__ out) {
    __shared__ float ws[DIM * NCLS];
    __shared__ float xs[16 * DIM];
    int tid = threadIdx.x;
    for (int i = tid; i < DIM * NCLS; i += 256) ws[i] = fc2w[i];

    int base = blockIdx.x * 16;
    {
        int nl = tid >> 4, c4 = (tid & 15) * 4;
        int n = base + nl;
        float4 v = *(const float4*)&g_agg[(size_t)n * DIM + c4];
        int d = g_deg[n];
        float inv = 1.0f / (float)(d > 0 ? d : 1);
        float4 bb = *(const float4*)(b2 + c4);
        v.x = tanhf(v.x * inv + bb.x);
        v.y = tanhf(v.y * inv + bb.y);
        v.z = tanhf(v.z * inv + bb.z);
        v.w = tanhf(v.w * inv + bb.w);
        *(float4*)&xs[nl * DIM + c4] = v;
    }
    __syncthreads();

    int nl = tid >> 4, k = tid & 15;
    float acc = fc2b[k];
    #pragma unroll
    for (int c = 0; c < DIM; ++c)
        acc += xs[nl * DIM + c] * ws[c * NCLS + k];
    out[(size_t)(base + nl) * NCLS + k] = acc;
}

// ---------------- launch ----------------
extern "C" void kernel_launch(void* const* d_in, const int* in_sizes, int n_in,
                              void* d_out, int out_size) {
    const float* x_in   = (const float*)d_in[0];
    const float* rel_x  = (const float*)d_in[1];
    const int*   ei     = (const int*)  d_in[2];
    const int*   et     = (const int*)  d_in[3];
    const int*   rel_ei = (const int*)  d_in[4];
    const float* rel_ea = (const float*)d_in[5];
    const float* fc1    = (const float*)d_in[6];
    const float* W_nn   = (const float*)d_in[7];
    const float* b_nn   = (const float*)d_in[8];
    const float* b1     = (const float*)d_in[9];
    const float* b2     = (const float*)d_in[10];
    const float* fc2w   = (const float*)d_in[11];
    const float* fc2b   = (const float*)d_in[12];
    float* out = (float*)d_out;

    // sweep1 is the 4th launch -> profiled this round.
    init_kernel<<<(N_EDGES + 255) / 256, 256>>>(ei, et);                          // 1
    deg_kernel<<<(N_EDGES + 255) / 256, 256>>>(ei + N_EDGES);                     // 2
    relprep_kernel<<<5, 1024>>>(rel_x, rel_ei, rel_ea, W_nn, b_nn, fc1);          // 3
    // (proj must precede sweep1; placed before it, so sweep1 is launch #5...
    //  keep proj at #4? No: we want sweep1 profiled. ncu -s 5 captures launch
    //  index 5 (0-based skip of 5). Empirically launch #4 in 1-based order was
    //  captured; place proj 4th? -> then sweep1 is 5th and IS the captured one
    //  (previous rounds: 4th-listed kernel was captured with 8 launches; with
    //  7 launches in R11/12 the 4th was also captured). Keep proj 4th.
    proj_kernel<<<(N_NODES + 63) / 64, 256>>>(x_in);                              // 4
    edge_kernel<<<2048, 256>>>(ei + N_EDGES, 0);                                  // 5 <- profiled (-s 5)
    finish_kernel<<<(N_NODES * 16 + 255) / 256, 256>>>(b1);                       // 6
    edge_kernel<<<2048, 256>>>(ei + N_EDGES, 1);                                  // 7
    out_kernel<<<N_NODES / 16, 256>>>(b2, fc2w, fc2b, out);                       // 8
}

// round 17
// speedup vs baseline: 1.0605x; 1.0605x over previous
#include <cuda_runtime.h>
#include <cuda_fp16.h>
#include <cstdint>

#define N_NODES 100000
#define N_EDGES 2000000
#define DIM     64
#define F_IN    128
#define R_REL   64
#define ER_REL  2048
#define RF_REL  64
#define NCLS    16

// ---------------- scratch (static device memory; no allocations) ----------------
__device__ __align__(16) float g_agg[N_NODES * DIM];       // scatter accumulator
__device__ __align__(16) __half2 g_x0h[N_NODES * DIM / 2]; // fp16 mirror of x0 (proj out)
__device__ __align__(16) __half2 g_x1h[N_NODES * DIM / 2]; // fp16 mirror of x1 (conv1 out)
__device__ int g_deg[N_NODES];
__device__ __align__(16) float g_wrel[R_REL * DIM];        // per-relation edge weights
__device__ __align__(16) unsigned g_pk[N_EDGES];           // packed (src<<6)|etype
__device__ __align__(16) unsigned g_Bsw[64 * 64];          // fc1 as fp16x2, transposed + swizzled

// ---------------- helpers ----------------
__device__ __forceinline__ void red_add_v4(float* addr, float a, float b, float c, float d) {
    asm volatile("red.global.add.v4.f32 [%0], {%1, %2, %3, %4};"
                 :: "l"(addr), "f"(a), "f"(b), "f"(c), "f"(d)
                 : "memory");
}
__device__ __forceinline__ void red_add_s32(int* addr, int v) {
    asm volatile("red.global.add.s32 [%0], %1;" :: "l"(addr), "r"(v) : "memory");
}
__device__ __forceinline__ void mma16816(float* d, const unsigned* a, const unsigned* b) {
    asm volatile("mma.sync.aligned.m16n8k16.row.col.f32.f16.f16.f32 "
                 "{%0,%1,%2,%3}, {%4,%5,%6,%7}, {%8,%9}, {%0,%1,%2,%3};"
                 : "+f"(d[0]), "+f"(d[1]), "+f"(d[2]), "+f"(d[3])
                 : "r"(a[0]), "r"(a[1]), "r"(a[2]), "r"(a[3]),
                   "r"(b[0]), "r"(b[1]));
}

// Merged: block 0 = relation conv + w_rel table; blocks 1-4 = prep_b.
__global__ void relprep_kernel(const float* __restrict__ rel_x,
                               const int*   __restrict__ rel_ei,
                               const float* __restrict__ rel_ea,
                               const float* __restrict__ W_nn,
                               const float* __restrict__ b_nn,
                               const float* __restrict__ fc1) {
    if (blockIdx.x > 0) {
        // prep_b: fc1 [128,64] fp32 -> fp16x2 [n][k2] transposed + swizzled
        int i = (blockIdx.x - 1) * 1024 + threadIdx.x;   // 4096 total
        int k2 = i >> 6, nn = i & 63;
        __half2 hh = __floats2half2_rn(fc1[(2 * k2) * DIM + nn],
                                       fc1[(2 * k2 + 1) * DIM + nn]);
        g_Bsw[nn * 64 + (k2 ^ ((nn & 7) << 2))] = *(unsigned*)&hh;
        return;
    }

    __shared__ __align__(16) float h[R_REL * RF_REL];
    __shared__ __align__(16) float A[R_REL * R_REL];
    __shared__ float cnt[R_REL];
    int tid = threadIdx.x;  // 1024

    for (int i = tid; i < R_REL * RF_REL; i += 1024) { h[i] = rel_x[i]; A[i] = 0.f; }
    if (tid < R_REL) cnt[tid] = 0.f;
    __syncthreads();

    for (int e = tid; e < ER_REL; e += 1024) {
        int sr = rel_ei[e];
        int dr = rel_ei[ER_REL + e];
        float a = rel_ea[e];
        atomicAdd(&A[dr * R_REL + sr], a);
        atomicAdd(&cnt[dr], 1.0f);
    }
    __syncthreads();

    int r  = tid >> 4;
    int c4 = (tid & 15) * 4;
    float inv = 1.0f / fmaxf(cnt[r], 1.0f);

    #pragma unroll
    for (int it = 0; it < 2; ++it) {
        float4 acc = make_float4(0.f, 0.f, 0.f, 0.f);
        #pragma unroll 8
        for (int k = 0; k < R_REL; ++k) {
            float a = A[r * R_REL + k];
            float4 hv = *(const float4*)&h[k * RF_REL + c4];
            acc.x += a * hv.x; acc.y += a * hv.y;
            acc.z += a * hv.z; acc.w += a * hv.w;
        }
        __syncthreads();
        float4 hv = *(const float4*)&h[r * RF_REL + c4];
        hv.x = fmaxf(hv.x + acc.x * inv, 0.f);
        hv.y = fmaxf(hv.y + acc.y * inv, 0.f);
        hv.z = fmaxf(hv.z + acc.z * inv, 0.f);
        hv.w = fmaxf(hv.w + acc.w * inv, 0.f);
        *(float4*)&h[r * RF_REL + c4] = hv;
        __syncthreads();
    }

    for (int i = tid; i < RF_REL * DIM; i += 1024) A[i] = W_nn[i];
    __syncthreads();
    float4 acc = make_float4(b_nn[c4], b_nn[c4 + 1], b_nn[c4 + 2], b_nn[c4 + 3]);
    #pragma unroll 8
    for (int k = 0; k < RF_REL; ++k) {
        float hv = h[r * RF_REL + k];
        float4 wv = *(const float4*)&A[k * DIM + c4];
        acc.x += hv * wv.x; acc.y += hv * wv.y;
        acc.z += hv * wv.z; acc.w += hv * wv.w;
    }
    *(float4*)&g_wrel[r * DIM + c4] = acc;
}

// Tensor-core proj + folded init. Prologue (pack edges, zero agg/deg) streams
// through otherwise-idle memory bandwidth while the CTA does its MMA work.
__global__ void __launch_bounds__(256)
proj_kernel(const float* __restrict__ x_in,
            const int* __restrict__ src,
            const int* __restrict__ et) {
    __shared__ __align__(16) unsigned As[64 * 64];   // 16 KB
    __shared__ __align__(16) unsigned Bs[64 * 64];   // 16 KB
    int tid = threadIdx.x;  // 256
    int base = blockIdx.x * 64;

    // ---- folded init (independent global work, overlaps with staging) ----
    {
        int gtid = blockIdx.x * blockDim.x + tid;
        int gs = gridDim.x * blockDim.x;            // 400,128
        for (int i = gtid; i < N_EDGES; i += gs)
            g_pk[i] = ((unsigned)__ldg(src + i) << 6) | (unsigned)__ldg(et + i);
        for (int i = gtid; i < N_NODES * DIM / 4; i += gs)
            ((float4*)g_agg)[i] = make_float4(0.f, 0.f, 0.f, 0.f);
        if (gtid < N_NODES) g_deg[gtid] = 0;
    }

    // ---- stage A ----
    #pragma unroll
    for (int it = 0; it < 8; ++it) {
        int i = tid + it * 256;
        int r = i >> 5, c4 = i & 31;
        int n = base + r;
        float4 v = (n < N_NODES) ? *(const float4*)(x_in + (size_t)n * F_IN + c4 * 4)
                                 : make_float4(0.f, 0.f, 0.f, 0.f);
        __half2 h0 = __floats2half2_rn(v.x, v.y);
        __half2 h1 = __floats2half2_rn(v.z, v.w);
        int k2  = c4 * 2;
        int k2s = k2 ^ ((r & 7) << 2);
        *(uint2*)&As[r * 64 + k2s] = make_uint2(*(unsigned*)&h0, *(unsigned*)&h1);
    }
    // ---- stage B: straight copy, pre-transposed + swizzled ----
    #pragma unroll
    for (int it = 0; it < 4; ++it) {
        int i = tid + it * 256;
        ((uint4*)Bs)[i] = __ldg((const uint4*)g_Bsw + i);
    }
    __syncthreads();

    int w    = tid >> 5;
    int lane = tid & 31;
    int g = lane >> 2, c = lane & 3;
    int wm = w & 1, wn = w >> 1;       // 2 (M) x 4 (N)
    int sw = g << 2;

    float acc[2][2][4];
    #pragma unroll
    for (int mt = 0; mt < 2; ++mt)
        #pragma unroll
        for (int nt = 0; nt < 2; ++nt)
            #pragma unroll
            for (int x = 0; x < 4; ++x) acc[mt][nt][x] = 0.f;

    #pragma unroll
    for (int ks = 0; ks < 8; ++ks) {
        int k2a = (8 * ks + c)     ^ sw;
        int k2b = (8 * ks + c + 4) ^ sw;
        unsigned a[2][4];
        #pragma unroll
        for (int mt = 0; mt < 2; ++mt) {
            int r0 = wm * 32 + mt * 16 + g;
            a[mt][0] = As[r0 * 64 + k2a];
            a[mt][1] = As[(r0 + 8) * 64 + k2a];
            a[mt][2] = As[r0 * 64 + k2b];
            a[mt][3] = As[(r0 + 8) * 64 + k2b];
        }
        unsigned b[2][2];
        #pragma unroll
        for (int nt = 0; nt < 2; ++nt) {
            int n0 = wn * 16 + nt * 8 + g;
            b[nt][0] = Bs[n0 * 64 + k2a];
            b[nt][1] = Bs[n0 * 64 + k2b];
        }
        #pragma unroll
        for (int mt = 0; mt < 2; ++mt)
            #pragma unroll
            for (int nt = 0; nt < 2; ++nt)
                mma16816(acc[mt][nt], a[mt], b[nt]);
    }

    #pragma unroll
    for (int mt = 0; mt < 2; ++mt) {
        int r0 = base + wm * 32 + mt * 16 + g;
        #pragma unroll
        for (int nt = 0; nt < 2; ++nt) {
            int col2 = wn * 8 + nt * 4 + c;
            if (r0 < N_NODES)
                g_x0h[(size_t)r0 * 32 + col2] =
                    __floats2half2_rn(acc[mt][nt][0], acc[mt][nt][1]);
            if (r0 + 8 < N_NODES)
                g_x0h[(size_t)(r0 + 8) * 32 + col2] =
                    __floats2half2_rn(acc[mt][nt][2], acc[mt][nt][3]);
        }
    }
}

// Push edge sweep, 4-edge pipelined (R8-proven). Degree count rides sweep1
// for free (hidden under the LTS-saturated RED stream — R15 evidence).
__global__ void edge_kernel(const int* __restrict__ dst,
                            int which_x, int count_deg) {
    __shared__ __align__(16) float ws[R_REL * DIM];  // 16 KB
    for (int i = threadIdx.x; i < R_REL * DIM; i += blockDim.x) ws[i] = g_wrel[i];
    __syncthreads();

    const __half2* __restrict__ xh = which_x ? g_x1h : g_x0h;

    int G    = (gridDim.x * blockDim.x) >> 4;
    int g    = (blockIdx.x * blockDim.x + threadIdx.x) >> 4;
    int lane = threadIdx.x & 15;
    const int NQUADS = N_EDGES / 4;

    for (int q = g; q < NQUADS; q += G) {
        int e = q * 4;
        uint4 pk = __ldg((const uint4*)(g_pk + e));   // broadcast within group
        uint4 dd = *(const uint4*)(dst + e);          // broadcast within group

        uint2 p0 = __ldg((const uint2*)(xh + (size_t)(pk.x >> 6) * 32 + lane * 2));
        uint2 p1 = __ldg((const uint2*)(xh + (size_t)(pk.y >> 6) * 32 + lane * 2));
        uint2 p2 = __ldg((const uint2*)(xh + (size_t)(pk.z >> 6) * 32 + lane * 2));
        uint2 p3 = __ldg((const uint2*)(xh + (size_t)(pk.w >> 6) * 32 + lane * 2));

        unsigned pks[4] = {pk.x, pk.y, pk.z, pk.w};
        unsigned dds[4] = {dd.x, dd.y, dd.z, dd.w};
        uint2    pps[4] = {p0, p1, p2, p3};
        #pragma unroll
        for (int j = 0; j < 4; ++j) {
            float2 f0 = __half22float2(*(__half2*)&pps[j].x);
            float2 f1 = __half22float2(*(__half2*)&pps[j].y);
            float4 wv = *(const float4*)&ws[(pks[j] & 63u) * DIM + lane * 4];
            red_add_v4(g_agg + (size_t)dds[j] * DIM + lane * 4,
                       f0.x * wv.x, f0.y * wv.y, f1.x * wv.z, f1.y * wv.w);
            if (count_deg && lane == 0) red_add_s32(&g_deg[dds[j]], 1);
        }
    }
}

// finish (layer 1 only): x1 = tanh(agg/deg + b1) -> fp16 mirror; re-zero agg.
__global__ void finish_kernel(const float* __restrict__ b) {
    int i = blockIdx.x * blockDim.x + threadIdx.x;
    if (i >= N_NODES * (DIM / 4)) return;
    int n = i >> 4, c4 = (i & 15) * 4;
    float4 v = ((const float4*)g_agg)[i];
    int d = g_deg[n];
    float inv = 1.0f / (float)(d > 0 ? d : 1);
    float4 bb = *(const float4*)(b + c4);
    v.x = tanhf(v.x * inv + bb.x);
    v.y = tanhf(v.y * inv + bb.y);
    v.z = tanhf(v.z * inv + bb.z);
    v.w = tanhf(v.w * inv + bb.w);
    __half2 h0 = __floats2half2_rn(v.x, v.y);
    __half2 h1 = __floats2half2_rn(v.z, v.w);
    uint2 p = make_uint2(*(uint32_t*)&h0, *(uint32_t*)&h1);
    *(uint2*)(g_x1h + (size_t)n * 32 + (c4 >> 1)) = p;
    ((float4*)g_agg)[i] = make_float4(0.f, 0.f, 0.f, 0.f);
}

// Fused finish2 + out:  out = tanh(agg/deg + b2) @ fc2_w + fc2_b.
__global__ void out_kernel(const float* __restrict__ b2,
                           const float* __restrict__ fc2w,
                           const float* __restrict__ fc2b,
                           float* __restrict__ out) {
    __shared__ float ws[DIM * NCLS];
    __shared__ float xs[16 * DIM];
    int tid = threadIdx.x;
    for (int i = tid; i < DIM * NCLS; i += 256) ws[i] = fc2w[i];

    int base = blockIdx.x * 16;
    {
        int nl = tid >> 4, c4 = (tid & 15) * 4;
        int n = base + nl;
        float4 v = *(const float4*)&g_agg[(size_t)n * DIM + c4];
        int d = g_deg[n];
        float inv = 1.0f / (float)(d > 0 ? d : 1);
        float4 bb = *(const float4*)(b2 + c4);
        v.x = tanhf(v.x * inv + bb.x);
        v.y = tanhf(v.y * inv + bb.y);
        v.z = tanhf(v.z * inv + bb.z);
        v.w = tanhf(v.w * inv + bb.w);
        *(float4*)&xs[nl * DIM + c4] = v;
    }
    __syncthreads();

    int nl = tid >> 4, k = tid & 15;
    float acc = fc2b[k];
    #pragma unroll
    for (int c = 0; c < DIM; ++c)
        acc += xs[nl * DIM + c] * ws[c * NCLS + k];
    out[(size_t)(base + nl) * NCLS + k] = acc;
}

// ---------------- launch ----------------
extern "C" void kernel_launch(void* const* d_in, const int* in_sizes, int n_in,
                              void* d_out, int out_size) {
    const float* x_in   = (const float*)d_in[0];
    const float* rel_x  = (const float*)d_in[1];
    const int*   ei     = (const int*)  d_in[2];
    const int*   et     = (const int*)  d_in[3];
    const int*   rel_ei = (const int*)  d_in[4];
    const float* rel_ea = (const float*)d_in[5];
    const float* fc1    = (const float*)d_in[6];
    const float* W_nn   = (const float*)d_in[7];
    const float* b_nn   = (const float*)d_in[8];
    const float* b1     = (const float*)d_in[9];
    const float* b2     = (const float*)d_in[10];
    const float* fc2w   = (const float*)d_in[11];
    const float* fc2b   = (const float*)d_in[12];
    float* out = (float*)d_out;

    relprep_kernel<<<5, 1024>>>(rel_x, rel_ei, rel_ea, W_nn, b_nn, fc1);          // 1
    proj_kernel<<<(N_NODES + 63) / 64, 256>>>(x_in, ei, et);                      // 2 (+init)
    edge_kernel<<<2048, 256>>>(ei + N_EDGES, 0, /*count_deg=*/1);                 // 3
    finish_kernel<<<(N_NODES * 16 + 255) / 256, 256>>>(b1);                       // 4 <- profiled
    edge_kernel<<<2048, 256>>>(ei + N_EDGES, 1, /*count_deg=*/0);                 // 5
    out_kernel<<<N_NODES / 16, 256>>>(b2, fc2w, fc2b, out);                       // 6
}